// round 15
// baseline (speedup 1.0000x reference)
#include <cuda_runtime.h>
#include <cuda_fp16.h>
#include <math.h>
#include <stdint.h>

#define NB 8
#define NC 512
#define HIN 32
#define HT 65
#define HO 64

// ---------------- scratch (device globals; no allocations allowed) ----------
__device__ uint32_t g_xs16[NB * 256 * HIN * HIN];  // x*s1, half2 pairs [b][cp][pix]
__device__ __half   g_t1h[NB * NC * HT * HT];      // conv1 output 65x65 (fp16)
__device__ uint32_t g_a1h[NB * 256 * HO * HO];     // blur out, half2 pairs [b][cp][pix]
__device__ uint32_t g_a2h[NB * 256 * HO * HO];     // conv2 out *s_rgb, half2 pairs
__device__ float    g_d1[NB * NC];
__device__ float    g_d2[NB * NC];
__device__ uint32_t g_wt16_1[512 * 2304];          // w1 half2 pairs [co][j*256+cp]
__device__ uint32_t g_wt16_2[512 * 2304];          // w2 half2 pairs
__device__ float    g_w2a[512 * 512];              // sum_j w1[co,ci,j]^2
__device__ float    g_w2b[512 * 512];              // sum_j w2[co,ci,j]^2

// ---------------- helpers ----------------------------------------------------
__device__ __forceinline__ void mma_f16(float* d, const uint32_t* a, const uint32_t* b) {
    asm volatile(
        "mma.sync.aligned.m16n8k16.row.col.f32.f16.f16.f32 "
        "{%0,%1,%2,%3}, {%4,%5,%6,%7}, {%8,%9}, {%0,%1,%2,%3};\n"
        : "+f"(d[0]), "+f"(d[1]), "+f"(d[2]), "+f"(d[3])
        : "r"(a[0]), "r"(a[1]), "r"(a[2]), "r"(a[3]), "r"(b[0]), "r"(b[1]));
}
__device__ __forceinline__ uint32_t packh2(float a, float b) {
    __half2 h = __floats2half2_rn(a, b);
    return *reinterpret_cast<uint32_t*>(&h);
}

// ---------------- K_wperm (both weight sets): wt16 + W2 ----------------------
__global__ void k_wperm(const float* __restrict__ w1, const float* __restrict__ w2,
                        uint32_t* __restrict__ wt1, uint32_t* __restrict__ wt2,
                        float* __restrict__ w2s1, float* __restrict__ w2s2) {
    __shared__ float row[4608];
    int co = blockIdx.x;
    const float* w = blockIdx.y ? w2 : w1;
    uint32_t*   wt = blockIdx.y ? wt2 : wt1;
    float*     w2s = blockIdx.y ? w2s2 : w2s1;
    const float* src = w + (size_t)co * 4608;
    for (int i = threadIdx.x; i < 4608; i += 256) row[i] = src[i];
    __syncthreads();
    uint32_t* dst = wt + (size_t)co * 2304;
    for (int m = threadIdx.x; m < 2304; m += 256) {
        int j = m >> 8, cp = m & 255;
        dst[m] = packh2(row[(2 * cp) * 9 + j], row[(2 * cp + 1) * 9 + j]);
    }
    for (int ci = threadIdx.x; ci < 512; ci += 256) {
        float s = 0.f;
#pragma unroll
        for (int j = 0; j < 9; j++) { float t = row[ci * 9 + j]; s += t * t; }
        w2s[(size_t)co * 512 + ci] = s;
    }
}

// ---------------- K_demod2 (both sets) ---------------------------------------
__global__ void k_demod2(const float* __restrict__ w2s1, const float* __restrict__ s1,
                         float* __restrict__ d1v,
                         const float* __restrict__ w2s2, const float* __restrict__ s2,
                         float* __restrict__ d2v, float scale) {
    int warp = threadIdx.x >> 5, lane = threadIdx.x & 31;
    int gid = blockIdx.x * 8 + warp;
    int b = gid >> 9, co = gid & 511;
    const float* w2s = blockIdx.y ? w2s2 : w2s1;
    const float* s   = blockIdx.y ? s2 : s1;
    float*       d   = blockIdx.y ? d2v : d1v;
    const float* wr = w2s + (size_t)co * 512;
    const float* sr = s + b * 512;
    float acc = 0.f;
#pragma unroll
    for (int i = lane; i < 512; i += 32) {
        float sv = sr[i];
        acc += wr[i] * sv * sv;
    }
#pragma unroll
    for (int off = 16; off > 0; off >>= 1)
        acc += __shfl_xor_sync(0xFFFFFFFFu, acc, off);
    if (lane == 0)
        d[b * 512 + co] = scale * rsqrtf(scale * scale * acc + 1e-8f);
}

// ---------------- K_scale: xs16[b][cp][pix] = half2(x*s1 pairs) --------------
__global__ void k_scale_x(const float* __restrict__ x, const float* __restrict__ s1,
                          uint32_t* __restrict__ xs) {
    int i = blockIdx.x * 256 + threadIdx.x;
    if (i < NB * 256 * HIN * HIN) {
        int pix = i & 1023;
        int cp  = (i >> 10) & 255;
        int b   = i >> 18;
        float sa = s1[b * 512 + 2 * cp];
        float sb = s1[b * 512 + 2 * cp + 1];
        const float* xb = x + ((size_t)(b * 512 + 2 * cp)) * 1024 + pix;
        xs[i] = packh2(xb[0] * sa, xb[1024] * sb);
    }
}

// ---------------- implicit-GEMM conv, FP16 m16n8k16 --------------------------
// Block 128(M) x 128(N), 128 threads (4 warps 2x2), warp tile 64x64.
// TWO CTAs per SM (regs*threads*2 <= 64K): independent barriers desync the
// crossbar and tensor phases across CTAs.
// A smem fragment-major (8 mblk x 128 per k8); B smem rotation swizzle (as R12).
template <int NTAPS, int EPI>
__global__ __launch_bounds__(128, 2) void conv_mma(
    const uint32_t* __restrict__ in, const uint32_t* __restrict__ wt,
    __half* __restrict__ out, const float* __restrict__ dmod,
    const float* __restrict__ noise, const float* __restrict__ nwp,
    const float* __restrict__ bias, const float* __restrict__ snext,
    int IH, int IW, int GH, int GW,
    int out_bstride, int out_cstride, int out_ys, int out_xs, int out_off,
    uint32_t pdy, uint32_t pdx, uint64_t pwo)
{
    __shared__ uint32_t As[2][2048];   // 2 kp8-blocks x 8 mblk x 128
    __shared__ uint32_t Bs[2][2048];   // fragment-major, rotation swizzle

    int tid  = threadIdx.x;
    int lane = tid & 31, warp = tid >> 5;
    int wm = warp >> 1, wn = warp & 1;   // 2(M) x 2(N) warp grid
    int kq = lane & 3, rq = lane >> 2;

    int b   = blockIdx.z;
    int co0 = blockIdx.y * 128;
    int n0  = blockIdx.x * 128;
    int GHW = GH * GW;
    int IHW = IH * IW;

    const uint32_t* inb = in + (size_t)b * 256 * IHW;

    // A loading: thread (akm 0..7, akk 0..15) -> rows akm + 8p + 16l
    int akm = tid >> 4;                  // 0..7
    int akk = tid & 15;
    const uint32_t* pA = wt + (size_t)(co0 + akm) * 2304 + akk;
    int a_stb = (akk >> 3) * 1024
              + ((akm * 4 + (akk & 3)) * 4)
              + 2 * ((akk >> 2) & 1);
    // element (p,l): smem a_stb + p + l*128, gmem + (8p+16l)*2304

    // B loading: thread -> pixel nl = tid, kp rows l = 0..15
    int nl  = tid;                       // 0..127
    int ng  = n0 + nl;
    int oy, ox;
    if (ng < GHW) { oy = ng / GW; ox = ng - oy * GW; }
    else          { oy = -100000; ox = 0; }
    int b_nblk = nl >> 3, b_rqb = nl & 7;

    float acc[4][8][4];
#pragma unroll
    for (int i = 0; i < 4; i++)
#pragma unroll
        for (int j = 0; j < 8; j++)
#pragma unroll
            for (int r = 0; r < 4; r++) acc[i][j][r] = 0.f;

    uint32_t pa[16];
    uint32_t pbv[16];

#pragma unroll 1
    for (int t = 0; t < NTAPS; t++) {
        int dy = (int)((pdy >> (2 * t)) & 3u) - 1;
        int dx = (int)((pdx >> (2 * t)) & 3u) - 1;
        int wo = (int)((pwo >> (4 * t)) & 15u);
        int iy = oy + dy, ix = ox + dx;
        bool bvalid = (iy >= 0) && (iy < IH) && (ix >= 0) && (ix < IW);
        const uint32_t* pAt = pA + wo * 256;
        const uint32_t* pBt = inb + iy * IW + ix;

        auto loadAB = [&](int kb2) {
            const uint32_t* pAk = pAt + kb2;
#pragma unroll
            for (int p = 0; p < 2; p++)
#pragma unroll
                for (int l = 0; l < 8; l++)
                    pa[p * 8 + l] = pAk[(size_t)(8 * p + 16 * l) * 2304];
            const uint32_t* pBk = pBt + (size_t)kb2 * IHW;
#pragma unroll
            for (int l = 0; l < 16; l++) {
                uint32_t v = 0u;
                if (bvalid) v = __ldg(pBk + (size_t)l * IHW);
                pbv[l] = v;
            }
        };
        auto storeAB = [&](int st) {
#pragma unroll
            for (int p = 0; p < 2; p++)
#pragma unroll
                for (int l = 0; l < 8; l++)
                    As[st][a_stb + p + l * 128] = pa[p * 8 + l];
#pragma unroll
            for (int l = 0; l < 16; l++) {
                int ks = l >> 3, kqv = l & 3, e = (l >> 2) & 1;
                int intra = (((b_rqb * 4 + kqv) * 2 + e) + 2 * b_nblk) & 63;
                Bs[st][(ks * 16 + b_nblk) * 64 + intra] = pbv[l];
            }
        };

        loadAB(0);
        storeAB(0);
        __syncthreads();

#pragma unroll 2
        for (int it2 = 0; it2 < 16; it2++) {
            int st = it2 & 1;
            if (it2 < 15) loadAB((it2 + 1) * 16);

            const uint32_t* Ap = As[st];
            const uint32_t* Bp = Bs[st];
#pragma unroll
            for (int ks = 0; ks < 2; ks++) {
                // B fragments loaded once, reused by all mt
                uint32_t bf[8][2];
#pragma unroll
                for (int nt = 0; nt < 8; nt++) {
                    int nblk = wn * 8 + nt;
                    int off = ((lane * 2) + 2 * nblk) & 63;
                    const uint2 v = *reinterpret_cast<const uint2*>(
                        &Bp[(ks * 16 + nblk) * 64 + off]);
                    bf[nt][0] = v.x; bf[nt][1] = v.y;
                }
                // A fragments ping-ponged at mt granularity
                uint32_t afc[4], afn[4];
                {
                    const uint4 v = *reinterpret_cast<const uint4*>(
                        &Ap[ks * 1024 + (wm * 4 + 0) * 128 + lane * 4]);
                    afc[0] = v.x; afc[1] = v.y; afc[2] = v.z; afc[3] = v.w;
                }
#pragma unroll
                for (int mt = 0; mt < 4; mt++) {
                    if (mt < 3) {
                        const uint4 v = *reinterpret_cast<const uint4*>(
                            &Ap[ks * 1024 + (wm * 4 + mt + 1) * 128 + lane * 4]);
                        afn[0] = v.x; afn[1] = v.y; afn[2] = v.z; afn[3] = v.w;
                    }
#pragma unroll
                    for (int nt = 0; nt < 8; nt++)
                        mma_f16(acc[mt][nt], afc, bf[nt]);
#pragma unroll
                    for (int e = 0; e < 4; e++) afc[e] = afn[e];
                }
            }

            if (it2 < 15) storeAB(st ^ 1);
            __syncthreads();
        }
    }

    // ---- epilogue ----
    const float SQRT2 = 1.41421356237309515f;
    int mbase = wm * 64, nbase = wn * 64;

    float nv[8][2];
    if (EPI == 1) {
        float nwv = nwp[0];
#pragma unroll
        for (int nt = 0; nt < 8; nt++)
#pragma unroll
            for (int j = 0; j < 2; j++) {
                int n = n0 + nbase + nt * 8 + kq * 2 + j;
                nv[nt][j] = (n < GHW) ? nwv * noise[b * GHW + n] : 0.f;
            }
    }

#pragma unroll
    for (int mt = 0; mt < 4; mt++) {
#pragma unroll
        for (int half = 0; half < 2; half++) {
            int co = co0 + mbase + mt * 16 + rq + half * 8;
            float dm = dmod[b * 512 + co];
            float bi = (EPI == 1) ? bias[co] : 0.f;
            float sn = (EPI == 1) ? snext[b * 512 + co] : 0.f;
#pragma unroll
            for (int nt = 0; nt < 8; nt++) {
#pragma unroll
                for (int j = 0; j < 2; j++) {
                    int n = n0 + nbase + nt * 8 + kq * 2 + j;
                    if (n < GHW) {
                        float v = acc[mt][nt][half * 2 + j] * dm;
                        if (EPI == 1) {
                            v += nv[nt][j] + bi;
                            v = (v >= 0.f ? v : 0.2f * v) * SQRT2;
                            v *= sn;
                            size_t adr = ((size_t)(b * 256 + (co >> 1)) * 4096 + n) * 2
                                       + (co & 1);
                            out[adr] = __float2half(v);
                        } else {
                            int oyp = n / GW;
                            int oxp = n - oyp * GW;
                            size_t adr = (size_t)b * out_bstride
                                       + (size_t)co * out_cstride
                                       + oyp * out_ys + oxp * out_xs + out_off;
                            out[adr] = __float2half(v);
                        }
                    }
                }
            }
        }
    }
}

// ---------------- K2: blur 4x4 (separable, smem) + noise + lrelu + s2 -------
__global__ __launch_bounds__(256) void k_blur(
    const __half* __restrict__ t1h, const float* __restrict__ n1,
    const float* __restrict__ nw1, const float* __restrict__ b1,
    const float* __restrict__ s2, uint32_t* __restrict__ a1h)
{
    __shared__ float raw[67 * 68];
    __shared__ float tmp[67 * 64];
    int tid = threadIdx.x;
    int c = blockIdx.x, b = blockIdx.y;
    const __half* tb = t1h + (size_t)(b * 512 + c) * (HT * HT);

    for (int i = tid; i < 67 * 67; i += 256) {
        int rr = i / 67, cc = i - rr * 67;
        int ty = rr - 1, tx = cc - 1;
        float v = 0.f;
        if (ty >= 0 && ty < HT && tx >= 0 && tx < HT)
            v = __half2float(tb[ty * HT + tx]);
        raw[rr * 68 + cc] = v;
    }
    __syncthreads();

    for (int i = tid; i < 67 * 64; i += 256) {
        int r = i >> 6, x = i & 63;
        const float* rp = &raw[r * 68 + x];
        tmp[i] = rp[0] + 3.f * rp[1] + 3.f * rp[2] + rp[3];
    }
    __syncthreads();

    float nwv = nw1[0];
    float bi  = b1[c];
    float s2v = s2[b * 512 + c];
    __half* ap = reinterpret_cast<__half*>(a1h)
               + ((size_t)(b * 256 + (c >> 1)) * 4096) * 2 + (c & 1);
    const float* np = n1 + (size_t)b * 4096;
    for (int pix = tid; pix < 4096; pix += 256) {
        int y = pix >> 6, x = pix & 63;
        float acc = tmp[y * 64 + x] + 3.f * tmp[(y + 1) * 64 + x]
                  + 3.f * tmp[(y + 2) * 64 + x] + tmp[(y + 3) * 64 + x];
        acc *= (1.f / 16.f);
        float v = acc + nwv * np[pix] + bi;
        v = (v >= 0.f ? v : 0.2f * v) * 1.41421356237309515f;
        ap[pix * 2] = __float2half(v * s2v);
    }
}

// ---------------- K4: ToRGB + bias + skip upfirdn up=2 ----------------------
__global__ void k_torgb(const uint32_t* __restrict__ a2h, const float* __restrict__ wrgb,
                        const float* __restrict__ brgb, const float* __restrict__ skip,
                        float* __restrict__ outp) {
    __shared__ float sw[1536];
    __shared__ float red[3][256];
    int tid = threadIdx.x;
    int b = blockIdx.y;
    const float srgb = 0.044194173824159216f;  // 1/sqrt(512)
    for (int i = tid; i < 1536; i += 256) sw[i] = wrgb[i] * srgb;
    __syncthreads();

    int p = tid & 63;
    int g = tid >> 6;
    int pix = blockIdx.x * 64 + p;
    const uint32_t* ab = a2h + (size_t)b * 256 * 4096 + pix;
    float acc0 = 0.f, acc1 = 0.f, acc2 = 0.f;
#pragma unroll 8
    for (int cp = g * 64; cp < g * 64 + 64; cp++) {
        uint32_t pv = ab[(size_t)cp * 4096];
        __half2 h = *reinterpret_cast<__half2*>(&pv);
        float lo = __half2float(__low2half(h));
        float hi = __half2float(__high2half(h));
        acc0 += sw[2 * cp] * lo + sw[2 * cp + 1] * hi;
        acc1 += sw[512 + 2 * cp] * lo + sw[512 + 2 * cp + 1] * hi;
        acc2 += sw[1024 + 2 * cp] * lo + sw[1024 + 2 * cp + 1] * hi;
    }
    red[0][tid] = acc0; red[1][tid] = acc1; red[2][tid] = acc2;
    __syncthreads();

    if (g == 0) {
        int y = pix >> 6, x = pix & 63;
        int iy0, iy1, ix0, ix1;
        float wy0, wy1, wx0, wx1;
        if ((y & 1) == 0) { iy0 = y / 2 - 1;   wy0 = 1.f; iy1 = y / 2;       wy1 = 3.f; }
        else              { iy0 = (y - 1) / 2; wy0 = 3.f; iy1 = (y + 1) / 2; wy1 = 1.f; }
        if ((x & 1) == 0) { ix0 = x / 2 - 1;   wx0 = 1.f; ix1 = x / 2;       wx1 = 3.f; }
        else              { ix0 = (x - 1) / 2; wx0 = 3.f; ix1 = (x + 1) / 2; wx1 = 1.f; }

#pragma unroll
        for (int o = 0; o < 3; o++) {
            float acc = red[o][p] + red[o][p + 64] + red[o][p + 128] + red[o][p + 192];
            const float* sb = skip + (size_t)(b * 3 + o) * 1024;
            float s = 0.f;
            if (iy0 >= 0 && iy0 < 32) {
                if (ix0 >= 0 && ix0 < 32) s += sb[iy0 * 32 + ix0] * wy0 * wx0;
                if (ix1 >= 0 && ix1 < 32) s += sb[iy0 * 32 + ix1] * wy0 * wx1;
            }
            if (iy1 >= 0 && iy1 < 32) {
                if (ix0 >= 0 && ix0 < 32) s += sb[iy1 * 32 + ix0] * wy1 * wx0;
                if (ix1 >= 0 && ix1 < 32) s += sb[iy1 * 32 + ix1] * wy1 * wx1;
            }
            s *= (1.f / 16.f);
            outp[(size_t)(b * 3 + o) * 4096 + pix] = acc + brgb[o] + s;
        }
    }
}

// ---------------- host-side tap packing --------------------------------------
static void pack_taps(const int* dy, const int* dx, const int* wo, int n,
                      uint32_t& pdy, uint32_t& pdx, uint64_t& pwo) {
    pdy = 0; pdx = 0; pwo = 0;
    for (int t = 0; t < n; t++) {
        pdy |= (uint32_t)(dy[t] + 1) << (2 * t);
        pdx |= (uint32_t)(dx[t] + 1) << (2 * t);
        pwo |= (uint64_t)(wo[t]) << (4 * t);
    }
}

// ---------------- launch -----------------------------------------------------
extern "C" void kernel_launch(void* const* d_in, const int* in_sizes, int n_in,
                              void* d_out, int out_size) {
    const float* x    = (const float*)d_in[0];
    const float* skip = (const float*)d_in[1];
    const float* w1   = (const float*)d_in[2];
    const float* b1   = (const float*)d_in[3];
    const float* s1   = (const float*)d_in[4];
    const float* nw1  = (const float*)d_in[5];
    const float* n1   = (const float*)d_in[6];
    const float* w2   = (const float*)d_in[7];
    const float* b2   = (const float*)d_in[8];
    const float* s2   = (const float*)d_in[9];
    const float* nw2  = (const float*)d_in[10];
    const float* n2   = (const float*)d_in[11];
    const float* wrgb = (const float*)d_in[12];
    const float* brgb = (const float*)d_in[13];
    const float* srgb = (const float*)d_in[14];
    float* outp = (float*)d_out;

    float *d1, *d2, *w2a, *w2b;
    uint32_t *xs16, *a1h, *a2h, *wt16_1, *wt16_2;
    __half* t1h;
    cudaGetSymbolAddress((void**)&xs16, g_xs16);
    cudaGetSymbolAddress((void**)&t1h, g_t1h);
    cudaGetSymbolAddress((void**)&a1h, g_a1h);
    cudaGetSymbolAddress((void**)&a2h, g_a2h);
    cudaGetSymbolAddress((void**)&d1, g_d1);
    cudaGetSymbolAddress((void**)&d2, g_d2);
    cudaGetSymbolAddress((void**)&wt16_1, g_wt16_1);
    cudaGetSymbolAddress((void**)&wt16_2, g_wt16_2);
    cudaGetSymbolAddress((void**)&w2a, g_w2a);
    cudaGetSymbolAddress((void**)&w2b, g_w2b);

    const float sc = 1.0f / sqrtf(512.0f * 9.0f);

    k_wperm<<<dim3(512, 2), 256>>>(w1, w2, wt16_1, wt16_2, w2a, w2b);
    k_scale_x<<<(NB * 256 * HIN * HIN + 255) / 256, 256>>>(x, s1, xs16);
    k_demod2<<<dim3(512, 2), 256>>>(w2a, s1, d1, w2b, s2, d2, sc);

    int bstride1 = NC * HT * HT;
    uint32_t pdy, pdx; uint64_t pwo;

    {   // phase (0,0): 4 taps, grid 33x33
        int dy[4] = {0, 0, -1, -1}, dx[4] = {0, -1, 0, -1}, wo[4] = {0, 2, 6, 8};
        pack_taps(dy, dx, wo, 4, pdy, pdx, pwo);
        conv_mma<4, 0><<<dim3((33 * 33 + 127) / 128, 4, NB), 128>>>(
            xs16, wt16_1, t1h, d1, nullptr, nullptr, nullptr, nullptr,
            HIN, HIN, 33, 33, bstride1, HT * HT, 2 * HT, 2, 0 * HT + 0, pdy, pdx, pwo);
    }
    {   // phase (0,1): 2 taps
        int dy[2] = {0, -1}, dx[2] = {0, 0}, wo[2] = {1, 7};
        pack_taps(dy, dx, wo, 2, pdy, pdx, pwo);
        conv_mma<2, 0><<<dim3((33 * 32 + 127) / 128, 4, NB), 128>>>(
            xs16, wt16_1, t1h, d1, nullptr, nullptr, nullptr, nullptr,
            HIN, HIN, 33, 32, bstride1, HT * HT, 2 * HT, 2, 0 * HT + 1, pdy, pdx, pwo);
    }
    {   // phase (1,0): 2 taps
        int dy[2] = {0, 0}, dx[2] = {0, -1}, wo[2] = {3, 5};
        pack_taps(dy, dx, wo, 2, pdy, pdx, pwo);
        conv_mma<2, 0><<<dim3((32 * 33 + 127) / 128, 4, NB), 128>>>(
            xs16, wt16_1, t1h, d1, nullptr, nullptr, nullptr, nullptr,
            HIN, HIN, 32, 33, bstride1, HT * HT, 2 * HT, 2, 1 * HT + 0, pdy, pdx, pwo);
    }
    {   // phase (1,1): 1 tap
        int dy[1] = {0}, dx[1] = {0}, wo[1] = {4};
        pack_taps(dy, dx, wo, 1, pdy, pdx, pwo);
        conv_mma<1, 0><<<dim3((32 * 32 + 127) / 128, 4, NB), 128>>>(
            xs16, wt16_1, t1h, d1, nullptr, nullptr, nullptr, nullptr,
            HIN, HIN, 32, 32, bstride1, HT * HT, 2 * HT, 2, 1 * HT + 1, pdy, pdx, pwo);
    }

    k_blur<<<dim3(NC, NB), 256>>>(t1h, n1, nw1, b1, s2, a1h);

    {   // conv2: 3x3 same, 9 taps -> a2h (pair-interleaved half)
        int dy[9], dx[9], wo[9];
        for (int t = 0; t < 9; t++) { dy[t] = t / 3 - 1; dx[t] = t % 3 - 1; wo[t] = t; }
        pack_taps(dy, dx, wo, 9, pdy, pdx, pwo);
        conv_mma<9, 1><<<dim3((HO * HO + 127) / 128, 4, NB), 128>>>(
            a1h, wt16_2, reinterpret_cast<__half*>(a2h), d2, n2, nw2, b2, srgb,
            HO, HO, HO, HO, 0, 0, 0, 0, 0, pdy, pdx, pwo);
    }

    k_torgb<<<dim3(64, NB), 256>>>(a2h, wrgb, brgb, skip, outp);
}

// round 17
// speedup vs baseline: 1.0449x; 1.0449x over previous
#include <cuda_runtime.h>
#include <cuda_fp16.h>
#include <math.h>
#include <stdint.h>

#define NB 8
#define NC 512
#define HIN 32
#define HT 65
#define HO 64

// ---------------- scratch (device globals; no allocations allowed) ----------
__device__ uint32_t g_xs16[NB * 256 * HIN * HIN];  // x*s1, half2 pairs [b][cp][pix]
__device__ __half   g_t1h[NB * NC * HT * HT];      // conv1 output 65x65 (fp16)
__device__ uint32_t g_a1h[NB * 256 * HO * HO];     // blur out, half2 pairs [b][cp][pix]
__device__ uint32_t g_a2h[NB * 256 * HO * HO];     // conv2 out *s_rgb, half2 pairs
__device__ float    g_d1[NB * NC];
__device__ float    g_d2[NB * NC];
__device__ uint32_t g_wt16_1[512 * 2304];          // w1 half2 pairs [co][j*256+cp]
__device__ uint32_t g_wt16_2[512 * 2304];          // w2 half2 pairs
__device__ float    g_w2a[512 * 512];              // sum_j w1[co,ci,j]^2
__device__ float    g_w2b[512 * 512];              // sum_j w2[co,ci,j]^2

// ---------------- helpers ----------------------------------------------------
__device__ __forceinline__ void mma_f16(float* d, const uint32_t* a, const uint32_t* b) {
    asm volatile(
        "mma.sync.aligned.m16n8k16.row.col.f32.f16.f16.f32 "
        "{%0,%1,%2,%3}, {%4,%5,%6,%7}, {%8,%9}, {%0,%1,%2,%3};\n"
        : "+f"(d[0]), "+f"(d[1]), "+f"(d[2]), "+f"(d[3])
        : "r"(a[0]), "r"(a[1]), "r"(a[2]), "r"(a[3]), "r"(b[0]), "r"(b[1]));
}
__device__ __forceinline__ uint32_t packh2(float a, float b) {
    __half2 h = __floats2half2_rn(a, b);
    return *reinterpret_cast<uint32_t*>(&h);
}

// ---------------- K_wperm (both weight sets): wt16 + W2 ----------------------
__global__ void k_wperm(const float* __restrict__ w1, const float* __restrict__ w2,
                        uint32_t* __restrict__ wt1, uint32_t* __restrict__ wt2,
                        float* __restrict__ w2s1, float* __restrict__ w2s2) {
    __shared__ float row[4608];
    int co = blockIdx.x;
    const float* w = blockIdx.y ? w2 : w1;
    uint32_t*   wt = blockIdx.y ? wt2 : wt1;
    float*     w2s = blockIdx.y ? w2s2 : w2s1;
    const float* src = w + (size_t)co * 4608;
    for (int i = threadIdx.x; i < 4608; i += 256) row[i] = src[i];
    __syncthreads();
    uint32_t* dst = wt + (size_t)co * 2304;
    for (int m = threadIdx.x; m < 2304; m += 256) {
        int j = m >> 8, cp = m & 255;
        dst[m] = packh2(row[(2 * cp) * 9 + j], row[(2 * cp + 1) * 9 + j]);
    }
    for (int ci = threadIdx.x; ci < 512; ci += 256) {
        float s = 0.f;
#pragma unroll
        for (int j = 0; j < 9; j++) { float t = row[ci * 9 + j]; s += t * t; }
        w2s[(size_t)co * 512 + ci] = s;
    }
}

// ---------------- K_demod2 (both sets) ---------------------------------------
__global__ void k_demod2(const float* __restrict__ w2s1, const float* __restrict__ s1,
                         float* __restrict__ d1v,
                         const float* __restrict__ w2s2, const float* __restrict__ s2,
                         float* __restrict__ d2v, float scale) {
    int warp = threadIdx.x >> 5, lane = threadIdx.x & 31;
    int gid = blockIdx.x * 8 + warp;
    int b = gid >> 9, co = gid & 511;
    const float* w2s = blockIdx.y ? w2s2 : w2s1;
    const float* s   = blockIdx.y ? s2 : s1;
    float*       d   = blockIdx.y ? d2v : d1v;
    const float* wr = w2s + (size_t)co * 512;
    const float* sr = s + b * 512;
    float acc = 0.f;
#pragma unroll
    for (int i = lane; i < 512; i += 32) {
        float sv = sr[i];
        acc += wr[i] * sv * sv;
    }
#pragma unroll
    for (int off = 16; off > 0; off >>= 1)
        acc += __shfl_xor_sync(0xFFFFFFFFu, acc, off);
    if (lane == 0)
        d[b * 512 + co] = scale * rsqrtf(scale * scale * acc + 1e-8f);
}

// ---------------- K_scale: xs16[b][cp][pix] = half2(x*s1 pairs) --------------
__global__ void k_scale_x(const float* __restrict__ x, const float* __restrict__ s1,
                          uint32_t* __restrict__ xs) {
    int i = blockIdx.x * 256 + threadIdx.x;
    if (i < NB * 256 * HIN * HIN) {
        int pix = i & 1023;
        int cp  = (i >> 10) & 255;
        int b   = i >> 18;
        float sa = s1[b * 512 + 2 * cp];
        float sb = s1[b * 512 + 2 * cp + 1];
        const float* xb = x + ((size_t)(b * 512 + 2 * cp)) * 1024 + pix;
        xs[i] = packh2(xb[0] * sa, xb[1024] * sb);
    }
}

// ---------------- implicit-GEMM conv, FP16 m16n8k16 --------------------------
// Block 256(M) x 128(N), 256 threads, warp grid 4(M)x2(N), warp tile 64x64.
// R12 layouts; fragment-consume with mt-granularity A ping-pong (R14).
template <int NTAPS, int EPI>
__global__ __launch_bounds__(256, 1) void conv_mma(
    const uint32_t* __restrict__ in, const uint32_t* __restrict__ wt,
    __half* __restrict__ out, const float* __restrict__ dmod,
    const float* __restrict__ noise, const float* __restrict__ nwp,
    const float* __restrict__ bias, const float* __restrict__ snext,
    int IH, int IW, int GH, int GW,
    int out_bstride, int out_cstride, int out_ys, int out_xs, int out_off,
    uint32_t pdy, uint32_t pdx, uint64_t pwo)
{
    __shared__ uint32_t As[2][4096];   // 2 kp8-blocks x 16 mblk x 128
    __shared__ uint32_t Bs[2][2048];   // fragment-major, rotation swizzle

    int tid  = threadIdx.x;
    int lane = tid & 31, warp = tid >> 5;
    int wm = warp >> 1, wn = warp & 1;   // 4(M) x 2(N) warp grid
    int kq = lane & 3, rq = lane >> 2;

    int b   = blockIdx.z;
    int co0 = blockIdx.y * 256;
    int n0  = blockIdx.x * 128;
    int GHW = GH * GW;
    int IHW = IH * IW;

    const uint32_t* inb = in + (size_t)b * 256 * IHW;

    // A loading: thread -> rows akm+16*l (l=0..15), kp-local akk (0..15)
    int akm = tid >> 4;                  // 0..15
    int akk = tid & 15;
    const uint32_t* pA = wt + (size_t)(co0 + akm) * 2304 + akk;
    int a_st = (akk >> 3) * 2048
             + (((akm & 7) * 4 + (akk & 3)) * 4)
             + ((akm >> 3) & 1) + 2 * ((akk >> 2) & 1);

    // B loading: thread -> pixel nl, kp rows bkl+2*l (l=0..7)
    int nl  = tid & 127;
    int bkl = tid >> 7;                  // 0..1
    int ng  = n0 + nl;
    int oy, ox;
    if (ng < GHW) { oy = ng / GW; ox = ng - oy * GW; }
    else          { oy = -100000; ox = 0; }
    int b_nblk = nl >> 3, b_rqb = nl & 7;

    float acc[4][8][4];
#pragma unroll
    for (int i = 0; i < 4; i++)
#pragma unroll
        for (int j = 0; j < 8; j++)
#pragma unroll
            for (int r = 0; r < 4; r++) acc[i][j][r] = 0.f;

    uint32_t pa[16];
    uint32_t pbv[8];

#pragma unroll 1
    for (int t = 0; t < NTAPS; t++) {
        int dy = (int)((pdy >> (2 * t)) & 3u) - 1;
        int dx = (int)((pdx >> (2 * t)) & 3u) - 1;
        int wo = (int)((pwo >> (4 * t)) & 15u);
        int iy = oy + dy, ix = ox + dx;
        bool bvalid = (iy >= 0) && (iy < IH) && (ix >= 0) && (ix < IW);
        const uint32_t* pAt = pA + wo * 256;
        const uint32_t* pBt = inb + iy * IW + ix;

        auto loadAB = [&](int kb2) {
            const uint32_t* pAk = pAt + kb2;
#pragma unroll
            for (int l = 0; l < 16; l++)
                pa[l] = pAk[(size_t)l * (16 * 2304)];
            const uint32_t* pBk = pBt + (size_t)(kb2 + bkl) * IHW;
#pragma unroll
            for (int l = 0; l < 8; l++) {
                uint32_t v = 0u;
                if (bvalid) v = __ldg(pBk + (size_t)(2 * l) * IHW);
                pbv[l] = v;
            }
        };
        auto storeAB = [&](int st) {
#pragma unroll
            for (int l = 0; l < 16; l++) As[st][a_st + l * 128] = pa[l];
#pragma unroll
            for (int l = 0; l < 8; l++) {
                int k = bkl + 2 * l;
                int ks = k >> 3, kqv = k & 3, e = (k >> 2) & 1;
                int intra = (((b_rqb * 4 + kqv) * 2 + e) + 2 * b_nblk) & 63;
                Bs[st][(ks * 16 + b_nblk) * 64 + intra] = pbv[l];
            }
        };

        loadAB(0);
        storeAB(0);
        __syncthreads();

#pragma unroll 2
        for (int it2 = 0; it2 < 16; it2++) {
            int st = it2 & 1;
            if (it2 < 15) loadAB((it2 + 1) * 16);

            const uint32_t* Ap = As[st];
            const uint32_t* Bp = Bs[st];
#pragma unroll
            for (int ks = 0; ks < 2; ks++) {
                // B fragments: loaded once, reused by all 4 mt
                uint32_t bf[8][2];
#pragma unroll
                for (int nt = 0; nt < 8; nt++) {
                    int nblk = wn * 8 + nt;
                    int off = ((lane * 2) + 2 * nblk) & 63;
                    const uint2 v = *reinterpret_cast<const uint2*>(
                        &Bp[(ks * 16 + nblk) * 64 + off]);
                    bf[nt][0] = v.x; bf[nt][1] = v.y;
                }
                // A fragments: ping-pong at mt granularity
                uint32_t afc[4], afn[4];
                {
                    const uint4 v = *reinterpret_cast<const uint4*>(
                        &Ap[ks * 2048 + (wm * 4 + 0) * 128 + lane * 4]);
                    afc[0] = v.x; afc[1] = v.y; afc[2] = v.z; afc[3] = v.w;
                }
#pragma unroll
                for (int mt = 0; mt < 4; mt++) {
                    if (mt < 3) {
                        const uint4 v = *reinterpret_cast<const uint4*>(
                            &Ap[ks * 2048 + (wm * 4 + mt + 1) * 128 + lane * 4]);
                        afn[0] = v.x; afn[1] = v.y; afn[2] = v.z; afn[3] = v.w;
                    }
#pragma unroll
                    for (int nt = 0; nt < 8; nt++)
                        mma_f16(acc[mt][nt], afc, bf[nt]);
#pragma unroll
                    for (int e = 0; e < 4; e++) afc[e] = afn[e];
                }
            }

            if (it2 < 15) storeAB(st ^ 1);
            __syncthreads();
        }
    }

    // ---- epilogue ----
    const float SQRT2 = 1.41421356237309515f;
    int mbase = wm * 64, nbase = wn * 64;

    float nv[8][2];
    if (EPI == 1) {
        float nwv = nwp[0];
#pragma unroll
        for (int nt = 0; nt < 8; nt++)
#pragma unroll
            for (int j = 0; j < 2; j++) {
                int n = n0 + nbase + nt * 8 + kq * 2 + j;
                nv[nt][j] = (n < GHW) ? nwv * noise[b * GHW + n] : 0.f;
            }
    }

#pragma unroll
    for (int mt = 0; mt < 4; mt++) {
#pragma unroll
        for (int half = 0; half < 2; half++) {
            int co = co0 + mbase + mt * 16 + rq + half * 8;
            float dm = dmod[b * 512 + co];
            float bi = (EPI == 1) ? bias[co] : 0.f;
            float sn = (EPI == 1) ? snext[b * 512 + co] : 0.f;
#pragma unroll
            for (int nt = 0; nt < 8; nt++) {
#pragma unroll
                for (int j = 0; j < 2; j++) {
                    int n = n0 + nbase + nt * 8 + kq * 2 + j;
                    if (n < GHW) {
                        float v = acc[mt][nt][half * 2 + j] * dm;
                        if (EPI == 1) {
                            v += nv[nt][j] + bi;
                            v = (v >= 0.f ? v : 0.2f * v) * SQRT2;
                            v *= sn;
                            size_t adr = ((size_t)(b * 256 + (co >> 1)) * 4096 + n) * 2
                                       + (co & 1);
                            out[adr] = __float2half(v);
                        } else {
                            int oyp = n / GW;
                            int oxp = n - oyp * GW;
                            size_t adr = (size_t)b * out_bstride
                                       + (size_t)co * out_cstride
                                       + oyp * out_ys + oxp * out_xs + out_off;
                            out[adr] = __float2half(v);
                        }
                    }
                }
            }
        }
    }
}

// ---------------- K2: blur (separable, smem), channel-pair, packed writes ---
// One block per (cp, b): processes channels 2cp and 2cp+1 sequentially,
// buffers results in registers, writes packed half2 words (coalesced).
__global__ __launch_bounds__(256) void k_blur(
    const __half* __restrict__ t1h, const float* __restrict__ n1,
    const float* __restrict__ nw1, const float* __restrict__ b1,
    const float* __restrict__ s2, uint32_t* __restrict__ a1h)
{
    __shared__ float raw[67 * 68];
    __shared__ float tmp[67 * 64];
    int tid = threadIdx.x;
    int cp = blockIdx.x, b = blockIdx.y;
    float nwv = nw1[0];
    const float* np = n1 + (size_t)b * 4096;

    float res[2][16];

#pragma unroll 1
    for (int sub = 0; sub < 2; sub++) {
        int c = 2 * cp + sub;
        const __half* tb = t1h + (size_t)(b * 512 + c) * (HT * HT);
        __syncthreads();   // protect raw/tmp reuse across sub iterations
        for (int i = tid; i < 67 * 67; i += 256) {
            int rr = i / 67, cc = i - rr * 67;
            int ty = rr - 1, tx = cc - 1;
            float v = 0.f;
            if (ty >= 0 && ty < HT && tx >= 0 && tx < HT)
                v = __half2float(tb[ty * HT + tx]);
            raw[rr * 68 + cc] = v;
        }
        __syncthreads();
        for (int i = tid; i < 67 * 64; i += 256) {
            int r = i >> 6, x = i & 63;
            const float* rp = &raw[r * 68 + x];
            tmp[i] = rp[0] + 3.f * rp[1] + 3.f * rp[2] + rp[3];
        }
        __syncthreads();
        float bi  = b1[c];
        float s2v = s2[b * 512 + c];
#pragma unroll
        for (int i = 0; i < 16; i++) {
            int pix = tid + i * 256;
            int y = pix >> 6, x = pix & 63;
            float acc = tmp[y * 64 + x] + 3.f * tmp[(y + 1) * 64 + x]
                      + 3.f * tmp[(y + 2) * 64 + x] + tmp[(y + 3) * 64 + x];
            acc *= (1.f / 16.f);
            float v = acc + nwv * np[pix] + bi;
            v = (v >= 0.f ? v : 0.2f * v) * 1.41421356237309515f;
            res[sub][i] = v * s2v;
        }
    }

    uint32_t* ap = a1h + (size_t)(b * 256 + cp) * 4096;
#pragma unroll
    for (int i = 0; i < 16; i++)
        ap[tid + i * 256] = packh2(res[0][i], res[1][i]);
}

// ---------------- K4: ToRGB + bias + skip upfirdn up=2 ----------------------
__global__ void k_torgb(const uint32_t* __restrict__ a2h, const float* __restrict__ wrgb,
                        const float* __restrict__ brgb, const float* __restrict__ skip,
                        float* __restrict__ outp) {
    __shared__ float sw[1536];
    __shared__ float red[3][256];
    int tid = threadIdx.x;
    int b = blockIdx.y;
    const float srgb = 0.044194173824159216f;  // 1/sqrt(512)
    for (int i = tid; i < 1536; i += 256) sw[i] = wrgb[i] * srgb;
    __syncthreads();

    int p = tid & 63;
    int g = tid >> 6;
    int pix = blockIdx.x * 64 + p;
    const uint32_t* ab = a2h + (size_t)b * 256 * 4096 + pix;
    float acc0 = 0.f, acc1 = 0.f, acc2 = 0.f;
#pragma unroll 8
    for (int cp = g * 64; cp < g * 64 + 64; cp++) {
        uint32_t pv = ab[(size_t)cp * 4096];
        __half2 h = *reinterpret_cast<__half2*>(&pv);
        float lo = __half2float(__low2half(h));
        float hi = __half2float(__high2half(h));
        acc0 += sw[2 * cp] * lo + sw[2 * cp + 1] * hi;
        acc1 += sw[512 + 2 * cp] * lo + sw[512 + 2 * cp + 1] * hi;
        acc2 += sw[1024 + 2 * cp] * lo + sw[1024 + 2 * cp + 1] * hi;
    }
    red[0][tid] = acc0; red[1][tid] = acc1; red[2][tid] = acc2;
    __syncthreads();

    if (g == 0) {
        int y = pix >> 6, x = pix & 63;
        int iy0, iy1, ix0, ix1;
        float wy0, wy1, wx0, wx1;
        if ((y & 1) == 0) { iy0 = y / 2 - 1;   wy0 = 1.f; iy1 = y / 2;       wy1 = 3.f; }
        else              { iy0 = (y - 1) / 2; wy0 = 3.f; iy1 = (y + 1) / 2; wy1 = 1.f; }
        if ((x & 1) == 0) { ix0 = x / 2 - 1;   wx0 = 1.f; ix1 = x / 2;       wx1 = 3.f; }
        else              { ix0 = (x - 1) / 2; wx0 = 3.f; ix1 = (x + 1) / 2; wx1 = 1.f; }

#pragma unroll
        for (int o = 0; o < 3; o++) {
            float acc = red[o][p] + red[o][p + 64] + red[o][p + 128] + red[o][p + 192];
            const float* sb = skip + (size_t)(b * 3 + o) * 1024;
            float s = 0.f;
            if (iy0 >= 0 && iy0 < 32) {
                if (ix0 >= 0 && ix0 < 32) s += sb[iy0 * 32 + ix0] * wy0 * wx0;
                if (ix1 >= 0 && ix1 < 32) s += sb[iy0 * 32 + ix1] * wy0 * wx1;
            }
            if (iy1 >= 0 && iy1 < 32) {
                if (ix0 >= 0 && ix0 < 32) s += sb[iy1 * 32 + ix0] * wy1 * wx0;
                if (ix1 >= 0 && ix1 < 32) s += sb[iy1 * 32 + ix1] * wy1 * wx1;
            }
            s *= (1.f / 16.f);
            outp[(size_t)(b * 3 + o) * 4096 + pix] = acc + brgb[o] + s;
        }
    }
}

// ---------------- host-side tap packing --------------------------------------
static void pack_taps(const int* dy, const int* dx, const int* wo, int n,
                      uint32_t& pdy, uint32_t& pdx, uint64_t& pwo) {
    pdy = 0; pdx = 0; pwo = 0;
    for (int t = 0; t < n; t++) {
        pdy |= (uint32_t)(dy[t] + 1) << (2 * t);
        pdx |= (uint32_t)(dx[t] + 1) << (2 * t);
        pwo |= (uint64_t)(wo[t]) << (4 * t);
    }
}

// ---------------- launch -----------------------------------------------------
extern "C" void kernel_launch(void* const* d_in, const int* in_sizes, int n_in,
                              void* d_out, int out_size) {
    const float* x    = (const float*)d_in[0];
    const float* skip = (const float*)d_in[1];
    const float* w1   = (const float*)d_in[2];
    const float* b1   = (const float*)d_in[3];
    const float* s1   = (const float*)d_in[4];
    const float* nw1  = (const float*)d_in[5];
    const float* n1   = (const float*)d_in[6];
    const float* w2   = (const float*)d_in[7];
    const float* b2   = (const float*)d_in[8];
    const float* s2   = (const float*)d_in[9];
    const float* nw2  = (const float*)d_in[10];
    const float* n2   = (const float*)d_in[11];
    const float* wrgb = (const float*)d_in[12];
    const float* brgb = (const float*)d_in[13];
    const float* srgb = (const float*)d_in[14];
    float* outp = (float*)d_out;

    float *d1, *d2, *w2a, *w2b;
    uint32_t *xs16, *a1h, *a2h, *wt16_1, *wt16_2;
    __half* t1h;
    cudaGetSymbolAddress((void**)&xs16, g_xs16);
    cudaGetSymbolAddress((void**)&t1h, g_t1h);
    cudaGetSymbolAddress((void**)&a1h, g_a1h);
    cudaGetSymbolAddress((void**)&a2h, g_a2h);
    cudaGetSymbolAddress((void**)&d1, g_d1);
    cudaGetSymbolAddress((void**)&d2, g_d2);
    cudaGetSymbolAddress((void**)&wt16_1, g_wt16_1);
    cudaGetSymbolAddress((void**)&wt16_2, g_wt16_2);
    cudaGetSymbolAddress((void**)&w2a, g_w2a);
    cudaGetSymbolAddress((void**)&w2b, g_w2b);

    const float sc = 1.0f / sqrtf(512.0f * 9.0f);

    k_wperm<<<dim3(512, 2), 256>>>(w1, w2, wt16_1, wt16_2, w2a, w2b);
    k_scale_x<<<(NB * 256 * HIN * HIN + 255) / 256, 256>>>(x, s1, xs16);
    k_demod2<<<dim3(512, 2), 256>>>(w2a, s1, d1, w2b, s2, d2, sc);

    int bstride1 = NC * HT * HT;
    uint32_t pdy, pdx; uint64_t pwo;

    {   // phase (0,0): 4 taps, grid 33x33
        int dy[4] = {0, 0, -1, -1}, dx[4] = {0, -1, 0, -1}, wo[4] = {0, 2, 6, 8};
        pack_taps(dy, dx, wo, 4, pdy, pdx, pwo);
        conv_mma<4, 0><<<dim3((33 * 33 + 127) / 128, 2, NB), 256>>>(
            xs16, wt16_1, t1h, d1, nullptr, nullptr, nullptr, nullptr,
            HIN, HIN, 33, 33, bstride1, HT * HT, 2 * HT, 2, 0 * HT + 0, pdy, pdx, pwo);
    }
    {   // phase (0,1): 2 taps
        int dy[2] = {0, -1}, dx[2] = {0, 0}, wo[2] = {1, 7};
        pack_taps(dy, dx, wo, 2, pdy, pdx, pwo);
        conv_mma<2, 0><<<dim3((33 * 32 + 127) / 128, 2, NB), 256>>>(
            xs16, wt16_1, t1h, d1, nullptr, nullptr, nullptr, nullptr,
            HIN, HIN, 33, 32, bstride1, HT * HT, 2 * HT, 2, 0 * HT + 1, pdy, pdx, pwo);
    }
    {   // phase (1,0): 2 taps
        int dy[2] = {0, 0}, dx[2] = {0, -1}, wo[2] = {3, 5};
        pack_taps(dy, dx, wo, 2, pdy, pdx, pwo);
        conv_mma<2, 0><<<dim3((32 * 33 + 127) / 128, 2, NB), 256>>>(
            xs16, wt16_1, t1h, d1, nullptr, nullptr, nullptr, nullptr,
            HIN, HIN, 32, 33, bstride1, HT * HT, 2 * HT, 2, 1 * HT + 0, pdy, pdx, pwo);
    }
    {   // phase (1,1): 1 tap
        int dy[1] = {0}, dx[1] = {0}, wo[1] = {4};
        pack_taps(dy, dx, wo, 1, pdy, pdx, pwo);
        conv_mma<1, 0><<<dim3((32 * 32 + 127) / 128, 2, NB), 256>>>(
            xs16, wt16_1, t1h, d1, nullptr, nullptr, nullptr, nullptr,
            HIN, HIN, 32, 32, bstride1, HT * HT, 2 * HT, 2, 1 * HT + 1, pdy, pdx, pwo);
    }

    k_blur<<<dim3(256, NB), 256>>>(t1h, n1, nw1, b1, s2, a1h);

    {   // conv2: 3x3 same, 9 taps -> a2h (pair-interleaved half)
        int dy[9], dx[9], wo[9];
        for (int t = 0; t < 9; t++) { dy[t] = t / 3 - 1; dx[t] = t % 3 - 1; wo[t] = t; }
        pack_taps(dy, dx, wo, 9, pdy, pdx, pwo);
        conv_mma<9, 1><<<dim3((HO * HO + 127) / 128, 2, NB), 256>>>(
            a1h, wt16_2, reinterpret_cast<__half*>(a2h), d2, n2, nw2, b2, srgb,
            HO, HO, HO, HO, 0, 0, 0, 0, 0, pdy, pdx, pwo);
    }

    k_torgb<<<dim3(64, NB), 256>>>(a2h, wrgb, brgb, skip, outp);
}